// round 8
// baseline (speedup 1.0000x reference)
#include <cuda_runtime.h>
#include <cstdint>

// LePEAttention, R8: legacy-path tensor cores (mma.sync tf32 — compute_103-legal,
// unlike tcgen05 which the harness's PTX target rejects).
// B=4, C=64, H=W=128, NUM_HEADS=8, hd=8, window 128x2=256 tokens.
// grid 4096 = 2048 workunits x 2 query-halves; 256 thr = 8 warps; warp owns 16
// query rows. QK = 3-term hi/lo tf32 MMA (error ~2^-22); exp on MUFU in regs;
// PV = packed-FFMA2 on exact fp32 V (consistent softmax num/denom); quad
// bfly-reduce; LePE 3x3 depthwise conv epilogue.

#define HW_ 16384
#define WW_ 128
#define CC_ 64

__device__ __forceinline__ unsigned long long pk2(float lo, float hi) {
    unsigned long long r;
    asm("mov.b64 %0, {%1, %2};" : "=l"(r) : "f"(lo), "f"(hi));
    return r;
}
__device__ __forceinline__ void upk2(unsigned long long v, float& lo, float& hi) {
    asm("mov.b64 {%0, %1}, %2;" : "=f"(lo), "=f"(hi) : "l"(v));
}
__device__ __forceinline__ unsigned long long ffma2(unsigned long long a, unsigned long long b, unsigned long long c) {
    unsigned long long d;
    asm("fma.rn.f32x2 %0, %1, %2, %3;" : "=l"(d) : "l"(a), "l"(b), "l"(c));
    return d;
}
__device__ __forceinline__ float ex2f(float x) { float r; asm("ex2.approx.f32 %0,%1;" : "=f"(r) : "f"(x)); return r; }
__device__ __forceinline__ uint32_t tf32rn(float x) { uint32_t r; asm("cvt.rna.tf32.f32 %0,%1;" : "=r"(r) : "f"(x)); return r; }

#define MMA8(c0,c1,c2,c3, a0,a1,a2,a3, b0,b1) \
    asm volatile("mma.sync.aligned.m16n8k8.row.col.f32.tf32.tf32.f32 " \
        "{%0,%1,%2,%3}, {%4,%5,%6,%7}, {%8,%9}, {%0,%1,%2,%3};" \
        : "+f"(c0), "+f"(c1), "+f"(c2), "+f"(c3) \
        : "r"(a0), "r"(a1), "r"(a2), "r"(a3), "r"(b0), "r"(b1))

__global__ void __launch_bounds__(256, 3)
lepe_mma(const float* __restrict__ temp,
         const float* __restrict__ cw,
         const float* __restrict__ cb,
         float* __restrict__ out)
{
    const int bid  = blockIdx.x;       // 0..4095
    const int wh   = bid >> 1;
    const int half = bid & 1;          // query half: tokens [half*128, half*128+128)
    const int h    = wh & 7;
    const int win  = wh >> 3;
    const int b    = win >> 6;
    const int wx   = win & 63;

    const int tid  = threadIdx.x;
    const int lane = tid & 31;
    const int w    = tid >> 5;         // warp 0..7
    const int g    = lane >> 2;        // row group 0..7
    const int q    = lane & 3;         // quad lane 0..3

    // QS/KS hold (tf32_hi, tf32_lo) pairs; vS holds exact V with 3 guard-zero
    // tokens each side (shared by PV and the LePE conv).
    __shared__ __align__(16) float2 QS[128*8];
    __shared__ __align__(16) float2 KS[256*8];
    __shared__ __align__(16) float  vS[262*8];
    __shared__ float wS[72];
    __shared__ float bS[8];

    if (tid < 24) { vS[tid] = 0.f; vS[262*8 - 24 + tid] = 0.f; }
    if (tid < 72) wS[tid] = cw[(h*8 + (tid & 7))*9 + (tid >> 3)];   // wS[tap*8+d]
    if (tid < 8)  bS[tid] = cb[h*8 + tid];

    const float qscale = 0.35355339059327373f * 1.44269504088896340736f; // 8^-0.5 * log2(e)

    // ---- Q: this CTA's 128 rows, scale folded, hi/lo tf32 split ----
    {
        const int m  = tid >> 1;
        const int ds = (tid & 1) * 4;
        const int tg = half*128 + m;
        const int y  = tg >> 1, x = 2*wx + (tg & 1);
        const float* qg = temp + ((size_t)(b*3 + 0)*CC_ + h*8)*HW_ + (size_t)y*WW_ + x;
        #pragma unroll
        for (int d2 = 0; d2 < 4; d2++) {
            int d = ds + d2;
            float v  = qg[(size_t)d*HW_] * qscale;
            float hi = __uint_as_float(tf32rn(v));
            float lo = __uint_as_float(tf32rn(v - hi));
            QS[m*8 + d] = make_float2(hi, lo);
        }
    }
    // ---- K: all 256 tokens, hi/lo tf32 split ----
    {
        const int tok = tid;
        const int y = tok >> 1, x = 2*wx + (tok & 1);
        const float* kg = temp + ((size_t)(b*3 + 1)*CC_ + h*8)*HW_ + (size_t)y*WW_ + x;
        #pragma unroll
        for (int d = 0; d < 8; d++) {
            float v  = kg[(size_t)d*HW_];
            float hi = __uint_as_float(tf32rn(v));
            float lo = __uint_as_float(tf32rn(v - hi));
            KS[tok*8 + d] = make_float2(hi, lo);
        }
    }
    // ---- V: all 256 tokens, exact fp32 ----
    {
        const int tok = tid;
        const int y = tok >> 1, x = 2*wx + (tok & 1);
        const float* vg = temp + ((size_t)(b*3 + 2)*CC_ + h*8)*HW_ + (size_t)y*WW_ + x;
        #pragma unroll
        for (int d = 0; d < 8; d++)
            vS[(tok + 3)*8 + d] = vg[(size_t)d*HW_];
    }
    __syncthreads();

    // ---- Q fragment (m16k8, rows w*16+g and +8, cols q and q+4), hi+lo ----
    const int r0 = w*16 + g;
    uint32_t a0h, a1h, a2h, a3h, a0l, a1l, a2l, a3l;
    {
        float2 f;
        f = QS[(r0    )*8 + q    ]; a0h = __float_as_uint(f.x); a0l = __float_as_uint(f.y);
        f = QS[(r0 + 8)*8 + q    ]; a1h = __float_as_uint(f.x); a1l = __float_as_uint(f.y);
        f = QS[(r0    )*8 + q + 4]; a2h = __float_as_uint(f.x); a2l = __float_as_uint(f.y);
        f = QS[(r0 + 8)*8 + q + 4]; a3h = __float_as_uint(f.x); a3l = __float_as_uint(f.y);
    }

    unsigned long long acc[8];
    #pragma unroll
    for (int i = 0; i < 8; i++) acc[i] = 0ull;
    float rs0 = 0.f, rs1 = 0.f;

    #pragma unroll 2
    for (int t = 0; t < 32; t++) {
        const int n0 = t*8;
        // B fragment (k8n8 col): key = n0+g, d = q / q+4
        float2 B0 = KS[(n0 + g)*8 + q];
        float2 B1 = KS[(n0 + g)*8 + q + 4];
        uint32_t b0h = __float_as_uint(B0.x), b0l = __float_as_uint(B0.y);
        uint32_t b1h = __float_as_uint(B1.x), b1l = __float_as_uint(B1.y);

        float c0 = 0.f, c1 = 0.f, c2 = 0.f, c3 = 0.f;
        MMA8(c0,c1,c2,c3, a0h,a1h,a2h,a3h, b0h,b1h);   // hi*hi
        MMA8(c0,c1,c2,c3, a0l,a1l,a2l,a3l, b0h,b1h);   // lo*hi
        MMA8(c0,c1,c2,c3, a0h,a1h,a2h,a3h, b0l,b1l);   // hi*lo

        // c0: (row r0,   col n0+2q), c1: col+1; c2/c3: row r0+8
        float p0 = ex2f(c0), p1 = ex2f(c1), p2 = ex2f(c2), p3 = ex2f(c3);
        rs0 += p0 + p1;
        rs1 += p2 + p3;

        const int c = n0 + 2*q;
        const ulonglong2 va = *(const ulonglong2*)&vS[(c + 3)*8];      // V[c][0..3]
        const ulonglong2 vb = *(const ulonglong2*)&vS[(c + 3)*8 + 4];  // V[c][4..7]
        const ulonglong2 vc_ = *(const ulonglong2*)&vS[(c + 4)*8];     // V[c+1][0..3]
        const ulonglong2 vd = *(const ulonglong2*)&vS[(c + 4)*8 + 4];  // V[c+1][4..7]

        unsigned long long pp;
        pp = pk2(p0, p0);
        acc[0] = ffma2(pp, va.x, acc[0]);  acc[1] = ffma2(pp, va.y, acc[1]);
        acc[2] = ffma2(pp, vb.x, acc[2]);  acc[3] = ffma2(pp, vb.y, acc[3]);
        pp = pk2(p1, p1);
        acc[0] = ffma2(pp, vc_.x, acc[0]); acc[1] = ffma2(pp, vc_.y, acc[1]);
        acc[2] = ffma2(pp, vd.x, acc[2]);  acc[3] = ffma2(pp, vd.y, acc[3]);
        pp = pk2(p2, p2);
        acc[4] = ffma2(pp, va.x, acc[4]);  acc[5] = ffma2(pp, va.y, acc[5]);
        acc[6] = ffma2(pp, vb.x, acc[6]);  acc[7] = ffma2(pp, vb.y, acc[7]);
        pp = pk2(p3, p3);
        acc[4] = ffma2(pp, vc_.x, acc[4]); acc[5] = ffma2(pp, vc_.y, acc[5]);
        acc[6] = ffma2(pp, vd.x, acc[6]);  acc[7] = ffma2(pp, vd.y, acc[7]);
    }

    // unpack + quad (lane%4) butterfly reduction: each quad's 4 lanes hold
    // disjoint key subsets of the same two rows.
    float o0[8], o1[8];
    upk2(acc[0], o0[0], o0[1]); upk2(acc[1], o0[2], o0[3]);
    upk2(acc[2], o0[4], o0[5]); upk2(acc[3], o0[6], o0[7]);
    upk2(acc[4], o1[0], o1[1]); upk2(acc[5], o1[2], o1[3]);
    upk2(acc[6], o1[4], o1[5]); upk2(acc[7], o1[6], o1[7]);

    #pragma unroll
    for (int x = 1; x <= 2; x <<= 1) {
        rs0 += __shfl_xor_sync(0xffffffffu, rs0, x);
        rs1 += __shfl_xor_sync(0xffffffffu, rs1, x);
        #pragma unroll
        for (int d = 0; d < 8; d++) {
            o0[d] += __shfl_xor_sync(0xffffffffu, o0[d], x);
            o1[d] += __shfl_xor_sync(0xffffffffu, o1[d], x);
        }
    }

    if (q == 0) {
        const float inv0 = 1.0f / rs0;
        const float inv1 = 1.0f / rs1;
        #pragma unroll
        for (int ri = 0; ri < 2; ri++) {
            const int   tok = half*128 + r0 + ri*8;
            const float inv = ri ? inv1 : inv0;
            const float* o  = ri ? o1 : o0;

            const int y  = tok >> 1;
            const int xi = tok & 1;
            float r[8];
            #pragma unroll
            for (int d = 0; d < 8; d++) r[d] = bS[d];
            #pragma unroll
            for (int ky = 0; ky < 3; ky++) {
                #pragma unroll
                for (int kx = 0; kx < 3; kx++) {
                    int dxi = xi + kx - 1;
                    if (dxi >= 0 && dxi <= 1) {
                        int ptok = tok + (ky - 1)*2 + (kx - 1) + 3;  // guarded index
                        const float4 va = *(const float4*)&vS[ptok*8];
                        const float4 vb = *(const float4*)&vS[ptok*8 + 4];
                        const float4 wa = *(const float4*)&wS[(ky*3 + kx)*8];
                        const float4 wb = *(const float4*)&wS[(ky*3 + kx)*8 + 4];
                        r[0] += va.x*wa.x;  r[1] += va.y*wa.y;
                        r[2] += va.z*wa.z;  r[3] += va.w*wa.w;
                        r[4] += vb.x*wb.x;  r[5] += vb.y*wb.y;
                        r[6] += vb.z*wb.z;  r[7] += vb.w*wb.w;
                    }
                }
            }

            const size_t obase = ((size_t)b*HW_ + (size_t)y*WW_ + 2*wx + xi)*CC_ + h*8;
            float4 w0 = make_float4(o[0]*inv + r[0], o[1]*inv + r[1],
                                    o[2]*inv + r[2], o[3]*inv + r[3]);
            float4 w1 = make_float4(o[4]*inv + r[4], o[5]*inv + r[5],
                                    o[6]*inv + r[6], o[7]*inv + r[7]);
            *(float4*)(out + obase)     = w0;
            *(float4*)(out + obase + 4) = w1;
        }
    }
}

extern "C" void kernel_launch(void* const* d_in, const int* in_sizes, int n_in,
                              void* d_out, int out_size)
{
    const float* temp = (const float*)d_in[0];
    const float* cw   = (const float*)d_in[1];
    const float* cb   = (const float*)d_in[2];
    float* out        = (float*)d_out;
    lepe_mma<<<4096, 256>>>(temp, cw, cb, out);
}

// round 10
// speedup vs baseline: 2.1459x; 2.1459x over previous
#include <cuda_runtime.h>
#include <cstdint>

// LePEAttention R10: R9 with the PV A-fragment scatter fixed (R9 left pv[2]
// uninitialized for sub=1 -> NaN). Full tensor-core chain, fragment-order smem.
// B=4, C=64, H=W=128, NUM_HEADS=8, hd=8, window 128x2 = 256 tokens.
// grid 4096 = 2048 workunits x 2 query-halves; 256 thr, warp owns 16 q-rows.
// QK: 3-term hi/lo tf32 m16n8k8. exp: MUFU in regs.
// PV: 3-term hi/lo bf16 m16n8k16, C-frag->A-frag layout chaining.
// K/V staged in smem in FRAGMENT order: 1 LDS.128 per 8-key tile (K) and per
// 16-key chunk (V) -- LDS instruction count was the R8 binder (L1 96.8%).

#define HW_ 16384
#define WW_ 128
#define CC_ 64

__device__ __forceinline__ float ex2f(float x) { float r; asm("ex2.approx.f32 %0,%1;" : "=f"(r) : "f"(x)); return r; }
__device__ __forceinline__ uint32_t tf32rn(float x) { uint32_t r; asm("cvt.rna.tf32.f32 %0,%1;" : "=r"(r) : "f"(x)); return r; }
// pack bf16x2 {lower16 = bf16(a), upper16 = bf16(b)}
__device__ __forceinline__ uint32_t bf2(float a, float b) {
    uint32_t r; asm("cvt.rn.bf16x2.f32 %0, %1, %2;" : "=r"(r) : "f"(b), "f"(a)); return r;
}
__device__ __forceinline__ float bflo(uint32_t v) { return __uint_as_float(v << 16); }
__device__ __forceinline__ float bfhi(uint32_t v) { return __uint_as_float(v & 0xffff0000u); }

#define MMA8(c0,c1,c2,c3, a0,a1,a2,a3, b0,b1) \
    asm volatile("mma.sync.aligned.m16n8k8.row.col.f32.tf32.tf32.f32 " \
        "{%0,%1,%2,%3}, {%4,%5,%6,%7}, {%8,%9}, {%0,%1,%2,%3};" \
        : "+f"(c0), "+f"(c1), "+f"(c2), "+f"(c3) \
        : "r"(a0), "r"(a1), "r"(a2), "r"(a3), "r"(b0), "r"(b1))

#define MMABF(c0,c1,c2,c3, a0,a1,a2,a3, b0,b1) \
    asm volatile("mma.sync.aligned.m16n8k16.row.col.f32.bf16.bf16.f32 " \
        "{%0,%1,%2,%3}, {%4,%5,%6,%7}, {%8,%9}, {%0,%1,%2,%3};" \
        : "+f"(c0), "+f"(c1), "+f"(c2), "+f"(c3) \
        : "r"(a0), "r"(a1), "r"(a2), "r"(a3), "r"(b0), "r"(b1))

__global__ void __launch_bounds__(256, 3)
lepe_mma2(const float* __restrict__ temp,
          const float* __restrict__ cw,
          const float* __restrict__ cb,
          float* __restrict__ out)
{
    const int bid  = blockIdx.x;       // 0..4095
    const int wh   = bid >> 1;
    const int half = bid & 1;
    const int h    = wh & 7;
    const int win  = wh >> 3;
    const int b    = win >> 6;
    const int wx   = win & 63;

    const int tid  = threadIdx.x;
    const int lane = tid & 31;
    const int w    = tid >> 5;
    const int g    = lane >> 2;        // row group 0..7
    const int q    = lane & 3;         // quad lane 0..3

    // KF[t][lane]: K frag for 8-key tile t: (hi@d=q, lo@d=q, hi@d=q+4, lo@d=q+4), key = 8t+g
    // VF[c][lane]: V bf16 frags for 16-key chunk c: (b0hi, b1hi, b0lo, b1lo), d = g
    __shared__ __align__(16) uint4  KF[32][32];     // 16 KB
    __shared__ __align__(16) uint4  VF[16][32];     // 8 KB
    __shared__ __align__(16) float2 QS[128*8];      // 8 KB (hi, lo)
    __shared__ __align__(16) float  vS[262*8];      // 8.4 KB exact V + 3 guard tokens/side
    __shared__ float wS[72];
    __shared__ float bS[8];

    if (tid < 24) { vS[tid] = 0.f; vS[262*8 - 24 + tid] = 0.f; }
    if (tid < 72) wS[tid] = cw[(h*8 + (tid & 7))*9 + (tid >> 3)];   // wS[tap*8+d]
    if (tid < 8)  bS[tid] = cb[h*8 + tid];

    const float qscale = 0.35355339059327373f * 1.44269504088896340736f; // 8^-0.5 * log2(e)

    // ---- Q: 128 rows of this half, scale folded, hi/lo tf32 ----
    {
        const int m  = tid >> 1;
        const int ds = (tid & 1) * 4;
        const int tg = half*128 + m;
        const int y  = tg >> 1, x = 2*wx + (tg & 1);
        const float* qg = temp + ((size_t)(b*3 + 0)*CC_ + h*8)*HW_ + (size_t)y*WW_ + x;
        #pragma unroll
        for (int d2 = 0; d2 < 4; d2++) {
            int d = ds + d2;
            float v  = qg[(size_t)d*HW_] * qscale;
            uint32_t hi = tf32rn(v);
            float lo = v - __uint_as_float(hi);
            QS[m*8 + d] = make_float2(__uint_as_float(hi), __uint_as_float(tf32rn(lo)));
        }
    }
    // ---- K: all 256 tokens -> fragment-order KF ----
    {
        const int tok = tid;
        const int y = tok >> 1, x = 2*wx + (tok & 1);
        const float* kg = temp + ((size_t)(b*3 + 1)*CC_ + h*8)*HW_ + (size_t)y*WW_ + x;
        uint32_t hi[8], lo[8];
        #pragma unroll
        for (int d = 0; d < 8; d++) {
            float v = kg[(size_t)d*HW_];
            hi[d] = tf32rn(v);
            lo[d] = tf32rn(v - __uint_as_float(hi[d]));
        }
        const int t = tok >> 3, gg = tok & 7;
        #pragma unroll
        for (int qq = 0; qq < 4; qq++)
            KF[t][gg*4 + qq] = make_uint4(hi[qq], lo[qq], hi[qq + 4], lo[qq + 4]);
    }
    // ---- V exact ----
    {
        const int tok = tid;
        const int y = tok >> 1, x = 2*wx + (tok & 1);
        const float* vg = temp + ((size_t)(b*3 + 2)*CC_ + h*8)*HW_ + (size_t)y*WW_ + x;
        #pragma unroll
        for (int d = 0; d < 8; d++)
            vS[(tok + 3)*8 + d] = vg[(size_t)d*HW_];
    }
    __syncthreads();

    // ---- V bf16 fragment packing (reads vS; tid<128, token pair 2u,2u+1) ----
    if (tid < 128) {
        const int u = tid;
        const int c = u >> 3, p = u & 7;
        const float* v0 = &vS[(2*u + 3)*8];
        const float* v1 = &vS[(2*u + 4)*8];
        uint32_t* VFu = (uint32_t*)VF;
        #pragma unroll
        for (int d = 0; d < 8; d++) {
            float a = v0[d], bb = v1[d];
            uint32_t hi2 = bf2(a, bb);                       // {lo=bf16(a), hi=bf16(bb)}
            uint32_t lo2 = bf2(a - bflo(hi2), bb - bfhi(hi2));
            // b0 covers local keys 2q,2q+1 (p<4, q=p); b1 covers 8+2q (p>=4, q=p-4)
            int lane_t = d*4 + (p & 3);
            int fld    = (p < 4) ? 0 : 1;                    // .x/.y = hi, .z/.w = lo
            VFu[(c*32 + lane_t)*4 + fld]     = hi2;
            VFu[(c*32 + lane_t)*4 + fld + 2] = lo2;
        }
    }
    __syncthreads();

    // ---- Q fragments (rows r0, r0+8; cols q, q+4; hi & lo) ----
    const int r0 = w*16 + g;
    uint32_t a0h, a1h, a2h, a3h, a0l, a1l, a2l, a3l;
    {
        float2 f;
        f = QS[(r0    )*8 + q    ]; a0h = __float_as_uint(f.x); a0l = __float_as_uint(f.y);
        f = QS[(r0 + 8)*8 + q    ]; a1h = __float_as_uint(f.x); a1l = __float_as_uint(f.y);
        f = QS[(r0    )*8 + q + 4]; a2h = __float_as_uint(f.x); a2l = __float_as_uint(f.y);
        f = QS[(r0 + 8)*8 + q + 4]; a3h = __float_as_uint(f.x); a3l = __float_as_uint(f.y);
    }

    float acc0 = 0.f, acc1 = 0.f, acc2 = 0.f, acc3 = 0.f;   // O frag: rows r0/r0+8, d=2q/2q+1
    float rs0 = 0.f, rs1 = 0.f;

    #pragma unroll 2
    for (int c16 = 0; c16 < 16; c16++) {
        // pv: PV A-frags (bf16x2). m16n8k16 A layout:
        //   a0 = (row g,   k 2q..2q+1)   -> h01 of sub0   -> pv[0]
        //   a1 = (row g+8, k 2q..2q+1)   -> h23 of sub0   -> pv[1]
        //   a2 = (row g,   k 8+2q..)     -> h01 of sub1   -> pv[2]
        //   a3 = (row g+8, k 8+2q..)     -> h23 of sub1   -> pv[3]
        // lo parts at pv[4..7] in the same order.
        uint32_t pv[8];
        #pragma unroll
        for (int sub = 0; sub < 2; sub++) {
            const int t = 2*c16 + sub;
            uint4 kf = KF[t][lane];
            float s0 = 0.f, s1 = 0.f, s2 = 0.f, s3 = 0.f;
            MMA8(s0,s1,s2,s3, a0h,a1h,a2h,a3h, kf.x, kf.z);   // hi*hi
            MMA8(s0,s1,s2,s3, a0l,a1l,a2l,a3l, kf.x, kf.z);   // lo*hi
            MMA8(s0,s1,s2,s3, a0h,a1h,a2h,a3h, kf.y, kf.w);   // hi*lo
            float p0 = ex2f(s0), p1 = ex2f(s1), p2 = ex2f(s2), p3 = ex2f(s3);
            rs0 += p0 + p1;
            rs1 += p2 + p3;
            uint32_t h01 = bf2(p0, p1);
            uint32_t h23 = bf2(p2, p3);
            uint32_t l01 = bf2(p0 - bflo(h01), p1 - bfhi(h01));
            uint32_t l23 = bf2(p2 - bflo(h23), p3 - bfhi(h23));
            pv[2*sub + 0] = h01;
            pv[2*sub + 1] = h23;
            pv[4 + 2*sub + 0] = l01;
            pv[4 + 2*sub + 1] = l23;
        }
        uint4 vf = VF[c16][lane];   // b0hi, b1hi, b0lo, b1lo
        MMABF(acc0,acc1,acc2,acc3, pv[0],pv[1],pv[2],pv[3], vf.x, vf.y);  // p_hi * v_hi
        MMABF(acc0,acc1,acc2,acc3, pv[4],pv[5],pv[6],pv[7], vf.x, vf.y);  // p_lo * v_hi
        MMABF(acc0,acc1,acc2,acc3, pv[0],pv[1],pv[2],pv[3], vf.z, vf.w);  // p_hi * v_lo
    }

    // row sums: quad butterfly (4 quads cover the 8 keys/tile -> all 256 keys)
    #pragma unroll
    for (int x = 1; x <= 2; x <<= 1) {
        rs0 += __shfl_xor_sync(0xffffffffu, rs0, x);
        rs1 += __shfl_xor_sync(0xffffffffu, rs1, x);
    }
    const float inv0 = 1.0f / rs0;
    const float inv1 = 1.0f / rs1;

    // ---- epilogue: every lane owns (rows r0, r0+8) x (d = 2q, 2q+1) ----
    float2 wp[9];
    #pragma unroll
    for (int tap = 0; tap < 9; tap++) wp[tap] = *(const float2*)&wS[tap*8 + 2*q];
    const float2 bias = *(const float2*)&bS[2*q];

    #pragma unroll
    for (int ri = 0; ri < 2; ri++) {
        const int   row = r0 + ri*8;
        const int   tok = half*128 + row;
        const float inv = ri ? inv1 : inv0;
        const float oc0 = (ri ? acc2 : acc0) * inv;
        const float oc1 = (ri ? acc3 : acc1) * inv;

        const int y  = tok >> 1;
        const int xi = tok & 1;
        float rx = bias.x, ry = bias.y;
        #pragma unroll
        for (int ky = 0; ky < 3; ky++) {
            #pragma unroll
            for (int kx = 0; kx < 3; kx++) {
                int dxi = xi + kx - 1;
                if (dxi >= 0 && dxi <= 1) {
                    int ptok = tok + (ky - 1)*2 + (kx - 1) + 3;
                    float2 v = *(const float2*)&vS[ptok*8 + 2*q];
                    float2 wv = wp[ky*3 + kx];
                    rx += v.x * wv.x;
                    ry += v.y * wv.y;
                }
            }
        }
        const size_t obase = ((size_t)b*HW_ + (size_t)y*WW_ + 2*wx + xi)*CC_ + h*8 + 2*q;
        *(float2*)(out + obase) = make_float2(oc0 + rx, oc1 + ry);
    }
}

extern "C" void kernel_launch(void* const* d_in, const int* in_sizes, int n_in,
                              void* d_out, int out_size)
{
    const float* temp = (const float*)d_in[0];
    const float* cw   = (const float*)d_in[1];
    const float* cb   = (const float*)d_in[2];
    float* out        = (float*)d_out;
    lepe_mma2<<<4096, 256>>>(temp, cw, cb, out);
}

// round 11
// speedup vs baseline: 2.5504x; 1.1885x over previous
#include <cuda_runtime.h>
#include <cuda_fp16.h>
#include <cstdint>

// LePEAttention R11: R10 + (1) fp16 dual-packed QK (A=[q_hi|q_lo] vs B=[k_hi|k_hi]
// then [k_lo|0] -> 2 MMAs/8-key tile instead of 3, KF uint4->uint2),
// (2) triple PV accumulators to break the serial MMABF chain,
// (3) launch_bounds(256,4) (smem ~29KB, fp16 A-frag frees regs).
// B=4, C=64, H=W=128, NUM_HEADS=8, hd=8, window 128x2 = 256 tokens.
// grid 4096 = 2048 workunits x 2 query-halves; 256 thr, warp owns 16 q-rows.

#define HW_ 16384
#define WW_ 128
#define CC_ 64

__device__ __forceinline__ float ex2f(float x) { float r; asm("ex2.approx.f32 %0,%1;" : "=f"(r) : "f"(x)); return r; }
// pack {lower16, upper16}
__device__ __forceinline__ uint32_t f16p(float lo_elem, float hi_elem) {
    uint32_t r; asm("cvt.rn.f16x2.f32 %0, %1, %2;" : "=r"(r) : "f"(hi_elem), "f"(lo_elem)); return r;
}
__device__ __forceinline__ float f16rt(float v) { return __half2float(__float2half_rn(v)); }
// bf16 helpers (PV path, proven in R10)
__device__ __forceinline__ uint32_t bf2(float a, float b) {
    uint32_t r; asm("cvt.rn.bf16x2.f32 %0, %1, %2;" : "=r"(r) : "f"(b), "f"(a)); return r;
}
__device__ __forceinline__ float bflo(uint32_t v) { return __uint_as_float(v << 16); }
__device__ __forceinline__ float bfhi(uint32_t v) { return __uint_as_float(v & 0xffff0000u); }

#define MMAF16(c0,c1,c2,c3, a0,a1,a2,a3, b0,b1) \
    asm volatile("mma.sync.aligned.m16n8k16.row.col.f32.f16.f16.f32 " \
        "{%0,%1,%2,%3}, {%4,%5,%6,%7}, {%8,%9}, {%0,%1,%2,%3};" \
        : "+f"(c0), "+f"(c1), "+f"(c2), "+f"(c3) \
        : "r"(a0), "r"(a1), "r"(a2), "r"(a3), "r"(b0), "r"(b1))

#define MMABF(c0,c1,c2,c3, a0,a1,a2,a3, b0,b1) \
    asm volatile("mma.sync.aligned.m16n8k16.row.col.f32.bf16.bf16.f32 " \
        "{%0,%1,%2,%3}, {%4,%5,%6,%7}, {%8,%9}, {%0,%1,%2,%3};" \
        : "+f"(c0), "+f"(c1), "+f"(c2), "+f"(c3) \
        : "r"(a0), "r"(a1), "r"(a2), "r"(a3), "r"(b0), "r"(b1))

__global__ void __launch_bounds__(256, 4)
lepe_mma3(const float* __restrict__ temp,
          const float* __restrict__ cw,
          const float* __restrict__ cb,
          float* __restrict__ out)
{
    const int bid  = blockIdx.x;       // 0..4095
    const int wh   = bid >> 1;
    const int half = bid & 1;
    const int h    = wh & 7;
    const int win  = wh >> 3;
    const int b    = win >> 6;
    const int wx   = win & 63;

    const int tid  = threadIdx.x;
    const int lane = tid & 31;
    const int w    = tid >> 5;
    const int g    = lane >> 2;        // row group 0..7
    const int q    = lane & 3;         // quad lane 0..3

    // KF[t][lane] = uint2{ pack(k_hi d=2q,2q+1), pack(k_lo d=2q,2q+1) }, key = 8t+g
    // VF[c][lane] = uint4{ b0hi, b1hi, b0lo, b1lo } bf16 V fragments, d = g
    // QS[m][0..3] = q_hi fp16x2 pairs (d01,d23,d45,d67); QS[m][4..7] = q_lo pairs
    __shared__ __align__(16) uint2    KF[32][32];    // 8 KB
    __shared__ __align__(16) uint4    VF[16][32];    // 8 KB
    __shared__ __align__(16) uint32_t QS[128*8];     // 4 KB
    __shared__ __align__(16) float    vS[262*8];     // 8.4 KB exact V + guard tokens
    __shared__ float wS[72];
    __shared__ float bS[8];

    if (tid < 24) { vS[tid] = 0.f; vS[262*8 - 24 + tid] = 0.f; }
    if (tid < 72) wS[tid] = cw[(h*8 + (tid & 7))*9 + (tid >> 3)];   // wS[tap*8+d]
    if (tid < 8)  bS[tid] = cb[h*8 + tid];

    const float qscale = 0.35355339059327373f * 1.44269504088896340736f; // 8^-0.5 * log2(e)

    // ---- Q: 128 rows of this half, scale folded, fp16 hi/lo packed pairs ----
    {
        const int m  = tid >> 1;
        const int ds = (tid & 1) * 4;        // 0 or 4
        const int tg = half*128 + m;
        const int y  = tg >> 1, x = 2*wx + (tg & 1);
        const float* qg = temp + ((size_t)(b*3 + 0)*CC_ + h*8)*HW_ + (size_t)y*WW_ + x;
        float v[4], hi[4];
        #pragma unroll
        for (int d2 = 0; d2 < 4; d2++) {
            v[d2]  = qg[(size_t)(ds + d2)*HW_] * qscale;
            hi[d2] = f16rt(v[d2]);
        }
        const int sl = ds >> 1;              // pair slot base: 0 or 2
        QS[m*8 + sl    ] = f16p(hi[0], hi[1]);
        QS[m*8 + sl + 1] = f16p(hi[2], hi[3]);
        QS[m*8 + 4 + sl    ] = f16p(v[0] - hi[0], v[1] - hi[1]);
        QS[m*8 + 4 + sl + 1] = f16p(v[2] - hi[2], v[3] - hi[3]);
    }
    // ---- K: all 256 tokens -> fp16 hi/lo fragment-order KF ----
    {
        const int tok = tid;
        const int y = tok >> 1, x = 2*wx + (tok & 1);
        const float* kg = temp + ((size_t)(b*3 + 1)*CC_ + h*8)*HW_ + (size_t)y*WW_ + x;
        float hi[8], lo[8];
        #pragma unroll
        for (int d = 0; d < 8; d++) {
            float v = kg[(size_t)d*HW_];
            hi[d] = f16rt(v);
            lo[d] = v - hi[d];
        }
        const int t = tok >> 3, gg = tok & 7;
        #pragma unroll
        for (int qq = 0; qq < 4; qq++)
            KF[t][gg*4 + qq] = make_uint2(f16p(hi[2*qq], hi[2*qq + 1]),
                                          f16p(lo[2*qq], lo[2*qq + 1]));
    }
    // ---- V exact ----
    {
        const int tok = tid;
        const int y = tok >> 1, x = 2*wx + (tok & 1);
        const float* vg = temp + ((size_t)(b*3 + 2)*CC_ + h*8)*HW_ + (size_t)y*WW_ + x;
        #pragma unroll
        for (int d = 0; d < 8; d++)
            vS[(tok + 3)*8 + d] = vg[(size_t)d*HW_];
    }
    __syncthreads();

    // ---- V bf16 fragment packing (unchanged from R10) ----
    if (tid < 128) {
        const int u = tid;
        const int c = u >> 3, p = u & 7;
        const float* v0 = &vS[(2*u + 3)*8];
        const float* v1 = &vS[(2*u + 4)*8];
        uint32_t* VFu = (uint32_t*)VF;
        #pragma unroll
        for (int d = 0; d < 8; d++) {
            float a = v0[d], bb = v1[d];
            uint32_t hi2 = bf2(a, bb);
            uint32_t lo2 = bf2(a - bflo(hi2), bb - bfhi(hi2));
            int lane_t = d*4 + (p & 3);
            int fld    = (p < 4) ? 0 : 1;
            VFu[(c*32 + lane_t)*4 + fld]     = hi2;
            VFu[(c*32 + lane_t)*4 + fld + 2] = lo2;
        }
    }
    __syncthreads();

    // ---- Q A-fragment: A = [q_hi (k 0..7) | q_lo (k 8..15)] ----
    const int r0 = w*16 + g;
    const uint32_t a0 = QS[(r0    )*8 + q];       // row g,   q_hi d=2q,2q+1
    const uint32_t a1 = QS[(r0 + 8)*8 + q];       // row g+8, q_hi
    const uint32_t a2 = QS[(r0    )*8 + 4 + q];   // row g,   q_lo
    const uint32_t a3 = QS[(r0 + 8)*8 + 4 + q];   // row g+8, q_lo
    const uint32_t ZR = 0;

    // PV accumulators: 3 independent sets (ph*vh, pl*vh, ph*vl)
    float aP0=0.f,aP1=0.f,aP2=0.f,aP3=0.f;
    float aQ0=0.f,aQ1=0.f,aQ2=0.f,aQ3=0.f;
    float aR0=0.f,aR1=0.f,aR2=0.f,aR3=0.f;
    float rs0 = 0.f, rs1 = 0.f;

    #pragma unroll 2
    for (int c16 = 0; c16 < 16; c16++) {
        uint32_t pv[8];
        #pragma unroll
        for (int sub = 0; sub < 2; sub++) {
            const int t = 2*c16 + sub;
            uint2 kf = KF[t][lane];
            float s0 = 0.f, s1 = 0.f, s2 = 0.f, s3 = 0.f;
            MMAF16(s0,s1,s2,s3, a0,a1,a2,a3, kf.x, kf.x);   // q_hi*k_hi + q_lo*k_hi
            MMAF16(s0,s1,s2,s3, a0,a1,a2,a3, kf.y, ZR);     // q_hi*k_lo
            float p0 = ex2f(s0), p1 = ex2f(s1), p2 = ex2f(s2), p3 = ex2f(s3);
            rs0 += p0 + p1;
            rs1 += p2 + p3;
            uint32_t h01 = bf2(p0, p1);
            uint32_t h23 = bf2(p2, p3);
            uint32_t l01 = bf2(p0 - bflo(h01), p1 - bfhi(h01));
            uint32_t l23 = bf2(p2 - bflo(h23), p3 - bfhi(h23));
            pv[2*sub + 0] = h01;
            pv[2*sub + 1] = h23;
            pv[4 + 2*sub + 0] = l01;
            pv[4 + 2*sub + 1] = l23;
        }
        uint4 vf = VF[c16][lane];
        MMABF(aP0,aP1,aP2,aP3, pv[0],pv[1],pv[2],pv[3], vf.x, vf.y);  // p_hi * v_hi
        MMABF(aQ0,aQ1,aQ2,aQ3, pv[4],pv[5],pv[6],pv[7], vf.x, vf.y);  // p_lo * v_hi
        MMABF(aR0,aR1,aR2,aR3, pv[0],pv[1],pv[2],pv[3], vf.z, vf.w);  // p_hi * v_lo
    }

    const float acc0 = aP0 + aQ0 + aR0;
    const float acc1 = aP1 + aQ1 + aR1;
    const float acc2 = aP2 + aQ2 + aR2;
    const float acc3 = aP3 + aQ3 + aR3;

    // row sums: quad butterfly
    #pragma unroll
    for (int x = 1; x <= 2; x <<= 1) {
        rs0 += __shfl_xor_sync(0xffffffffu, rs0, x);
        rs1 += __shfl_xor_sync(0xffffffffu, rs1, x);
    }
    const float inv0 = 1.0f / rs0;
    const float inv1 = 1.0f / rs1;

    // ---- epilogue: every lane owns (rows r0, r0+8) x (d = 2q, 2q+1) ----
    float2 wp[9];
    #pragma unroll
    for (int tap = 0; tap < 9; tap++) wp[tap] = *(const float2*)&wS[tap*8 + 2*q];
    const float2 bias = *(const float2*)&bS[2*q];

    #pragma unroll
    for (int ri = 0; ri < 2; ri++) {
        const int   row = r0 + ri*8;
        const int   tok = half*128 + row;
        const float inv = ri ? inv1 : inv0;
        const float oc0 = (ri ? acc2 : acc0) * inv;
        const float oc1 = (ri ? acc3 : acc1) * inv;

        const int y  = tok >> 1;
        const int xi = tok & 1;
        float rx = bias.x, ry = bias.y;
        #pragma unroll
        for (int ky = 0; ky < 3; ky++) {
            #pragma unroll
            for (int kx = 0; kx < 3; kx++) {
                int dxi = xi + kx - 1;
                if (dxi >= 0 && dxi <= 1) {
                    int ptok = tok + (ky - 1)*2 + (kx - 1) + 3;
                    float2 v = *(const float2*)&vS[ptok*8 + 2*q];
                    float2 wv = wp[ky*3 + kx];
                    rx += v.x * wv.x;
                    ry += v.y * wv.y;
                }
            }
        }
        const size_t obase = ((size_t)b*HW_ + (size_t)y*WW_ + 2*wx + xi)*CC_ + h*8 + 2*q;
        *(float2*)(out + obase) = make_float2(oc0 + rx, oc1 + ry);
    }
}

extern "C" void kernel_launch(void* const* d_in, const int* in_sizes, int n_in,
                              void* d_out, int out_size)
{
    const float* temp = (const float*)d_in[0];
    const float* cw   = (const float*)d_in[1];
    const float* cb   = (const float*)d_in[2];
    float* out        = (float*)d_out;
    lepe_mma3<<<4096, 256>>>(temp, cw, cb, out);
}

// round 12
// speedup vs baseline: 2.9827x; 1.1695x over previous
#include <cuda_runtime.h>
#include <cuda_fp16.h>
#include <cstdint>

// LePEAttention R12: merge the two query-half CTAs -> one CTA per workunit
// (grid 2048, 256 thr). Each warp owns 32 query rows as two m16 blocks that
// SHARE the KF/VF B-fragments -> K/V global loads, K/V STS, and inner-loop
// LDS per unit work all halve (load-phase L1 wavefronts were the R11 binder).
// QK: fp16 dual-packed hi/lo (A=[q_hi|q_lo] vs B=[k_hi|k_hi], [k_lo|0]).
// PV: 3-term hi/lo bf16 m16n8k16 (2 accumulator sets per block).
// B=4, C=64, H=W=128, NUM_HEADS=8, hd=8, window 128x2 = 256 tokens.

#define HW_ 16384
#define WW_ 128
#define CC_ 64

__device__ __forceinline__ float ex2f(float x) { float r; asm("ex2.approx.f32 %0,%1;" : "=f"(r) : "f"(x)); return r; }
__device__ __forceinline__ uint32_t f16p(float lo_elem, float hi_elem) {
    uint32_t r; asm("cvt.rn.f16x2.f32 %0, %1, %2;" : "=r"(r) : "f"(hi_elem), "f"(lo_elem)); return r;
}
__device__ __forceinline__ float f16rt(float v) { return __half2float(__float2half_rn(v)); }
__device__ __forceinline__ uint32_t bf2(float a, float b) {
    uint32_t r; asm("cvt.rn.bf16x2.f32 %0, %1, %2;" : "=r"(r) : "f"(b), "f"(a)); return r;
}
__device__ __forceinline__ float bflo(uint32_t v) { return __uint_as_float(v << 16); }
__device__ __forceinline__ float bfhi(uint32_t v) { return __uint_as_float(v & 0xffff0000u); }

#define MMAF16(c0,c1,c2,c3, a0,a1,a2,a3, b0,b1) \
    asm volatile("mma.sync.aligned.m16n8k16.row.col.f32.f16.f16.f32 " \
        "{%0,%1,%2,%3}, {%4,%5,%6,%7}, {%8,%9}, {%0,%1,%2,%3};" \
        : "+f"(c0), "+f"(c1), "+f"(c2), "+f"(c3) \
        : "r"(a0), "r"(a1), "r"(a2), "r"(a3), "r"(b0), "r"(b1))

#define MMABF(c0,c1,c2,c3, a0,a1,a2,a3, b0,b1) \
    asm volatile("mma.sync.aligned.m16n8k16.row.col.f32.bf16.bf16.f32 " \
        "{%0,%1,%2,%3}, {%4,%5,%6,%7}, {%8,%9}, {%0,%1,%2,%3};" \
        : "+f"(c0), "+f"(c1), "+f"(c2), "+f"(c3) \
        : "r"(a0), "r"(a1), "r"(a2), "r"(a3), "r"(b0), "r"(b1))

__global__ void __launch_bounds__(256, 3)
lepe_mma4(const float* __restrict__ temp,
          const float* __restrict__ cw,
          const float* __restrict__ cb,
          float* __restrict__ out)
{
    const int wh  = blockIdx.x;        // 0..2047
    const int h   = wh & 7;
    const int win = wh >> 3;
    const int b   = win >> 6;
    const int wx  = win & 63;

    const int tid  = threadIdx.x;
    const int lane = tid & 31;
    const int w    = tid >> 5;
    const int g    = lane >> 2;        // row group 0..7
    const int q    = lane & 3;         // quad lane 0..3

    // KF[t][lane] = uint2{ pack(k_hi d=2q,2q+1), pack(k_lo) }, key = 8t+g
    // VF[c][lane] = uint4{ b0hi, b1hi, b0lo, b1lo } bf16 V fragments, d = g
    // QS[m][0..3] = q_hi fp16x2 pairs; QS[m][4..7] = q_lo pairs (m = 0..255)
    __shared__ __align__(16) uint2    KF[32][32];    // 8 KB
    __shared__ __align__(16) uint4    VF[16][32];    // 8 KB
    __shared__ __align__(16) uint32_t QS[256*8];     // 8 KB
    __shared__ __align__(16) float    vS[262*8];     // 8.4 KB exact V + guard tokens
    __shared__ float wS[72];
    __shared__ float bS[8];

    if (tid < 24) { vS[tid] = 0.f; vS[262*8 - 24 + tid] = 0.f; }
    if (tid < 72) wS[tid] = cw[(h*8 + (tid & 7))*9 + (tid >> 3)];   // wS[tap*8+d]
    if (tid < 8)  bS[tid] = cb[h*8 + tid];

    const float qscale = 0.35355339059327373f * 1.44269504088896340736f; // 8^-0.5 * log2(e)

    // ---- Q: all 256 rows, one row per thread, fp16 hi/lo packed pairs ----
    {
        const int m = tid;
        const int y = m >> 1, x = 2*wx + (m & 1);
        const float* qg = temp + ((size_t)(b*3 + 0)*CC_ + h*8)*HW_ + (size_t)y*WW_ + x;
        float v[8], hi[8];
        #pragma unroll
        for (int d = 0; d < 8; d++) {
            v[d]  = qg[(size_t)d*HW_] * qscale;
            hi[d] = f16rt(v[d]);
        }
        #pragma unroll
        for (int j = 0; j < 4; j++) {
            QS[m*8 + j]     = f16p(hi[2*j], hi[2*j + 1]);
            QS[m*8 + 4 + j] = f16p(v[2*j] - hi[2*j], v[2*j + 1] - hi[2*j + 1]);
        }
    }
    // ---- K: one token per thread -> fp16 hi/lo fragment-order KF ----
    {
        const int tok = tid;
        const int y = tok >> 1, x = 2*wx + (tok & 1);
        const float* kg = temp + ((size_t)(b*3 + 1)*CC_ + h*8)*HW_ + (size_t)y*WW_ + x;
        float hi[8], lo[8];
        #pragma unroll
        for (int d = 0; d < 8; d++) {
            float v = kg[(size_t)d*HW_];
            hi[d] = f16rt(v);
            lo[d] = v - hi[d];
        }
        const int t = tok >> 3, gg = tok & 7;
        #pragma unroll
        for (int qq = 0; qq < 4; qq++)
            KF[t][gg*4 + qq] = make_uint2(f16p(hi[2*qq], hi[2*qq + 1]),
                                          f16p(lo[2*qq], lo[2*qq + 1]));
    }
    // ---- V exact ----
    {
        const int tok = tid;
        const int y = tok >> 1, x = 2*wx + (tok & 1);
        const float* vg = temp + ((size_t)(b*3 + 2)*CC_ + h*8)*HW_ + (size_t)y*WW_ + x;
        #pragma unroll
        for (int d = 0; d < 8; d++)
            vS[(tok + 3)*8 + d] = vg[(size_t)d*HW_];
    }
    __syncthreads();

    // ---- V bf16 fragment packing ----
    if (tid < 128) {
        const int u = tid;
        const int c = u >> 3, p = u & 7;
        const float* v0 = &vS[(2*u + 3)*8];
        const float* v1 = &vS[(2*u + 4)*8];
        uint32_t* VFu = (uint32_t*)VF;
        #pragma unroll
        for (int d = 0; d < 8; d++) {
            float a = v0[d], bb = v1[d];
            uint32_t hi2 = bf2(a, bb);
            uint32_t lo2 = bf2(a - bflo(hi2), bb - bfhi(hi2));
            int lane_t = d*4 + (p & 3);
            int fld    = (p < 4) ? 0 : 1;
            VFu[(c*32 + lane_t)*4 + fld]     = hi2;
            VFu[(c*32 + lane_t)*4 + fld + 2] = lo2;
        }
    }
    __syncthreads();

    // ---- A-fragments for the warp's two row blocks: rows [w*32, +16), [w*32+16, +16) ----
    const int R0 = w*32, R1 = w*32 + 16;
    const uint32_t aA0 = QS[(R0 + g    )*8 + q];
    const uint32_t aA1 = QS[(R0 + g + 8)*8 + q];
    const uint32_t aA2 = QS[(R0 + g    )*8 + 4 + q];
    const uint32_t aA3 = QS[(R0 + g + 8)*8 + 4 + q];
    const uint32_t aB0 = QS[(R1 + g    )*8 + q];
    const uint32_t aB1 = QS[(R1 + g + 8)*8 + q];
    const uint32_t aB2 = QS[(R1 + g    )*8 + 4 + q];
    const uint32_t aB3 = QS[(R1 + g + 8)*8 + 4 + q];
    const uint32_t ZR = 0;

    // accumulators: per block, main (ph*vh) + correction (pl*vh, ph*vl)
    float mA0=0.f,mA1=0.f,mA2=0.f,mA3=0.f, cA0=0.f,cA1=0.f,cA2=0.f,cA3=0.f;
    float mB0=0.f,mB1=0.f,mB2=0.f,mB3=0.f, cB0=0.f,cB1=0.f,cB2=0.f,cB3=0.f;
    float rsA0=0.f, rsA1=0.f, rsB0=0.f, rsB1=0.f;

    #pragma unroll 2
    for (int c16 = 0; c16 < 16; c16++) {
        uint32_t pvA[8], pvB[8];
        #pragma unroll
        for (int sub = 0; sub < 2; sub++) {
            uint2 kf = KF[2*c16 + sub][lane];
            {   // block A
                float s0=0.f,s1=0.f,s2=0.f,s3=0.f;
                MMAF16(s0,s1,s2,s3, aA0,aA1,aA2,aA3, kf.x, kf.x);
                MMAF16(s0,s1,s2,s3, aA0,aA1,aA2,aA3, kf.y, ZR);
                float p0=ex2f(s0), p1=ex2f(s1), p2=ex2f(s2), p3=ex2f(s3);
                rsA0 += p0 + p1;  rsA1 += p2 + p3;
                uint32_t h01 = bf2(p0,p1), h23 = bf2(p2,p3);
                pvA[2*sub]   = h01;
                pvA[2*sub+1] = h23;
                pvA[4+2*sub]   = bf2(p0 - bflo(h01), p1 - bfhi(h01));
                pvA[4+2*sub+1] = bf2(p2 - bflo(h23), p3 - bfhi(h23));
            }
            {   // block B
                float s0=0.f,s1=0.f,s2=0.f,s3=0.f;
                MMAF16(s0,s1,s2,s3, aB0,aB1,aB2,aB3, kf.x, kf.x);
                MMAF16(s0,s1,s2,s3, aB0,aB1,aB2,aB3, kf.y, ZR);
                float p0=ex2f(s0), p1=ex2f(s1), p2=ex2f(s2), p3=ex2f(s3);
                rsB0 += p0 + p1;  rsB1 += p2 + p3;
                uint32_t h01 = bf2(p0,p1), h23 = bf2(p2,p3);
                pvB[2*sub]   = h01;
                pvB[2*sub+1] = h23;
                pvB[4+2*sub]   = bf2(p0 - bflo(h01), p1 - bfhi(h01));
                pvB[4+2*sub+1] = bf2(p2 - bflo(h23), p3 - bfhi(h23));
            }
        }
        uint4 vf = VF[c16][lane];
        MMABF(mA0,mA1,mA2,mA3, pvA[0],pvA[1],pvA[2],pvA[3], vf.x, vf.y);  // ph*vh
        MMABF(cA0,cA1,cA2,cA3, pvA[4],pvA[5],pvA[6],pvA[7], vf.x, vf.y);  // pl*vh
        MMABF(cA0,cA1,cA2,cA3, pvA[0],pvA[1],pvA[2],pvA[3], vf.z, vf.w);  // ph*vl
        MMABF(mB0,mB1,mB2,mB3, pvB[0],pvB[1],pvB[2],pvB[3], vf.x, vf.y);
        MMABF(cB0,cB1,cB2,cB3, pvB[4],pvB[5],pvB[6],pvB[7], vf.x, vf.y);
        MMABF(cB0,cB1,cB2,cB3, pvB[0],pvB[1],pvB[2],pvB[3], vf.z, vf.w);
    }

    // row sums: quad butterfly
    #pragma unroll
    for (int x = 1; x <= 2; x <<= 1) {
        rsA0 += __shfl_xor_sync(0xffffffffu, rsA0, x);
        rsA1 += __shfl_xor_sync(0xffffffffu, rsA1, x);
        rsB0 += __shfl_xor_sync(0xffffffffu, rsB0, x);
        rsB1 += __shfl_xor_sync(0xffffffffu, rsB1, x);
    }

    // ---- epilogue: lane owns 4 rows x (d = 2q, 2q+1) ----
    float2 wp[9];
    #pragma unroll
    for (int tap = 0; tap < 9; tap++) wp[tap] = *(const float2*)&wS[tap*8 + 2*q];
    const float2 bias = *(const float2*)&bS[2*q];

    const float oc[4][2] = {
        { (mA0 + cA0) / rsA0, (mA1 + cA1) / rsA0 },
        { (mA2 + cA2) / rsA1, (mA3 + cA3) / rsA1 },
        { (mB0 + cB0) / rsB0, (mB1 + cB1) / rsB0 },
        { (mB2 + cB2) / rsB1, (mB3 + cB3) / rsB1 },
    };
    const int rows[4] = { R0 + g, R0 + g + 8, R1 + g, R1 + g + 8 };

    #pragma unroll
    for (int ri = 0; ri < 4; ri++) {
        const int tok = rows[ri];
        const int y  = tok >> 1;
        const int xi = tok & 1;
        float rx = bias.x, ry = bias.y;
        #pragma unroll
        for (int ky = 0; ky < 3; ky++) {
            #pragma unroll
            for (int kx = 0; kx < 3; kx++) {
                int dxi = xi + kx - 1;
                if (dxi >= 0 && dxi <= 1) {
                    int ptok = tok + (ky - 1)*2 + (kx - 1) + 3;
                    float2 v = *(const float2*)&vS[ptok*8 + 2*q];
                    float2 wv = wp[ky*3 + kx];
                    rx += v.x * wv.x;
                    ry += v.y * wv.y;
                }
            }
        }
        const size_t obase = ((size_t)b*HW_ + (size_t)y*WW_ + 2*wx + xi)*CC_ + h*8 + 2*q;
        *(float2*)(out + obase) = make_float2(oc[ri][0] + rx, oc[ri][1] + ry);
    }
}

extern "C" void kernel_launch(void* const* d_in, const int* in_sizes, int n_in,
                              void* d_out, int out_size)
{
    const float* temp = (const float*)d_in[0];
    const float* cw   = (const float*)d_in[1];
    const float* cb   = (const float*)d_in[2];
    float* out        = (float*)d_out;
    lepe_mma4<<<2048, 256>>>(temp, cw, cb, out);
}

// round 13
// speedup vs baseline: 4.1155x; 1.3798x over previous
#include <cuda_runtime.h>
#include <cuda_fp16.h>
#include <cstdint>

// LePEAttention R13: precision-trimmed tensor chain. R12 spent 8 of 14 MMAs +
// 32 pack/sub ops per c16 on hi/lo corrections for rel_err 1.6e-6 vs a 1e-3
// gate. Now: QK = ONE fp16 m16n8k16 (A=[q_hi|q_lo] vs B=[k|k]: q_lo correction
// free, only q*k_lo dropped ~7e-4 logit noise -> consistent softmax perturbation
// ~5e-5 out). PV = ONE fp16 MMA (p,V fp16, fp32 accum ~7e-5). Est rel ~1.5e-4.
// MMAs/c16 14->6, packs 16->8, subs 16->0, KF->uint32, VF->uint2, accs 16->8.
// LePE conv keeps exact fp32 V. grid 2048 (CTA = full workunit), 256 thr.

#define HW_ 16384
#define WW_ 128
#define CC_ 64

__device__ __forceinline__ float ex2f(float x) { float r; asm("ex2.approx.f32 %0,%1;" : "=f"(r) : "f"(x)); return r; }
// pack fp16x2 {lower16 = fp16(lo_elem), upper16 = fp16(hi_elem)}
__device__ __forceinline__ uint32_t f16p(float lo_elem, float hi_elem) {
    uint32_t r; asm("cvt.rn.f16x2.f32 %0, %1, %2;" : "=r"(r) : "f"(hi_elem), "f"(lo_elem)); return r;
}
__device__ __forceinline__ float f16rt(float v) { return __half2float(__float2half_rn(v)); }

#define MMAF16(c0,c1,c2,c3, a0,a1,a2,a3, b0,b1) \
    asm volatile("mma.sync.aligned.m16n8k16.row.col.f32.f16.f16.f32 " \
        "{%0,%1,%2,%3}, {%4,%5,%6,%7}, {%8,%9}, {%0,%1,%2,%3};" \
        : "+f"(c0), "+f"(c1), "+f"(c2), "+f"(c3) \
        : "r"(a0), "r"(a1), "r"(a2), "r"(a3), "r"(b0), "r"(b1))

__global__ void __launch_bounds__(256, 4)
lepe_mma5(const float* __restrict__ temp,
          const float* __restrict__ cw,
          const float* __restrict__ cb,
          float* __restrict__ out)
{
    const int wh  = blockIdx.x;        // 0..2047
    const int h   = wh & 7;
    const int win = wh >> 3;
    const int b   = win >> 6;
    const int wx  = win & 63;

    const int tid  = threadIdx.x;
    const int lane = tid & 31;
    const int w    = tid >> 5;
    const int g    = lane >> 2;        // row group 0..7
    const int q    = lane & 3;         // quad lane 0..3

    // KF[t][lane] = fp16x2 pack of k[8t+g][d=2q,2q+1]
    // VF[c][lane] = uint2{ b0, b1 } fp16 V fragments for 16-key chunk c, d = g
    // QS[m][0..3] = q_hi fp16x2 pairs; QS[m][4..7] = q_lo pairs (m = 0..255)
    __shared__ __align__(16) uint32_t KF[32][32];    // 4 KB
    __shared__ __align__(16) uint2    VF[16][32];    // 4 KB
    __shared__ __align__(16) uint32_t QS[256*8];     // 8 KB
    __shared__ __align__(16) float    vS[262*8];     // 8.4 KB exact V + guard tokens
    __shared__ float wS[72];
    __shared__ float bS[8];

    if (tid < 24) { vS[tid] = 0.f; vS[262*8 - 24 + tid] = 0.f; }
    if (tid < 72) wS[tid] = cw[(h*8 + (tid & 7))*9 + (tid >> 3)];   // wS[tap*8+d]
    if (tid < 8)  bS[tid] = cb[h*8 + tid];

    const float qscale = 0.35355339059327373f * 1.44269504088896340736f; // 8^-0.5 * log2(e)

    // ---- Q: all 256 rows, one row per thread, fp16 hi/lo packed pairs ----
    {
        const int m = tid;
        const int y = m >> 1, x = 2*wx + (m & 1);
        const float* qg = temp + ((size_t)(b*3 + 0)*CC_ + h*8)*HW_ + (size_t)y*WW_ + x;
        float v[8], hi[8];
        #pragma unroll
        for (int d = 0; d < 8; d++) {
            v[d]  = qg[(size_t)d*HW_] * qscale;
            hi[d] = f16rt(v[d]);
        }
        #pragma unroll
        for (int j = 0; j < 4; j++) {
            QS[m*8 + j]     = f16p(hi[2*j], hi[2*j + 1]);
            QS[m*8 + 4 + j] = f16p(v[2*j] - hi[2*j], v[2*j + 1] - hi[2*j + 1]);
        }
    }
    // ---- K: one token per thread -> fp16 fragment-order KF ----
    {
        const int tok = tid;
        const int y = tok >> 1, x = 2*wx + (tok & 1);
        const float* kg = temp + ((size_t)(b*3 + 1)*CC_ + h*8)*HW_ + (size_t)y*WW_ + x;
        float kv[8];
        #pragma unroll
        for (int d = 0; d < 8; d++) kv[d] = kg[(size_t)d*HW_];
        const int t = tok >> 3, gg = tok & 7;
        #pragma unroll
        for (int qq = 0; qq < 4; qq++)
            KF[t][gg*4 + qq] = f16p(kv[2*qq], kv[2*qq + 1]);
    }
    // ---- V exact ----
    {
        const int tok = tid;
        const int y = tok >> 1, x = 2*wx + (tok & 1);
        const float* vg = temp + ((size_t)(b*3 + 2)*CC_ + h*8)*HW_ + (size_t)y*WW_ + x;
        #pragma unroll
        for (int d = 0; d < 8; d++)
            vS[(tok + 3)*8 + d] = vg[(size_t)d*HW_];
    }
    __syncthreads();

    // ---- V fp16 fragment packing (d = g plane; token pair 2u, 2u+1) ----
    if (tid < 128) {
        const int u = tid;
        const int c = u >> 3, p = u & 7;
        const float* v0 = &vS[(2*u + 3)*8];
        const float* v1 = &vS[(2*u + 4)*8];
        uint32_t* VFu = (uint32_t*)VF;
        #pragma unroll
        for (int d = 0; d < 8; d++) {
            uint32_t pk = f16p(v0[d], v1[d]);
            int lane_t = d*4 + (p & 3);
            int fld    = (p < 4) ? 0 : 1;       // .x = b0 (k rows 2q..), .y = b1 (k rows 8+2q..)
            VFu[(c*32 + lane_t)*2 + fld] = pk;
        }
    }
    __syncthreads();

    // ---- A-fragments for the warp's two row blocks ----
    const int R0 = w*32, R1 = w*32 + 16;
    const uint32_t aA0 = QS[(R0 + g    )*8 + q];
    const uint32_t aA1 = QS[(R0 + g + 8)*8 + q];
    const uint32_t aA2 = QS[(R0 + g    )*8 + 4 + q];
    const uint32_t aA3 = QS[(R0 + g + 8)*8 + 4 + q];
    const uint32_t aB0 = QS[(R1 + g    )*8 + q];
    const uint32_t aB1 = QS[(R1 + g + 8)*8 + q];
    const uint32_t aB2 = QS[(R1 + g    )*8 + 4 + q];
    const uint32_t aB3 = QS[(R1 + g + 8)*8 + 4 + q];

    float mA0=0.f,mA1=0.f,mA2=0.f,mA3=0.f;
    float mB0=0.f,mB1=0.f,mB2=0.f,mB3=0.f;
    float rsA0=0.f, rsA1=0.f, rsB0=0.f, rsB1=0.f;

    #pragma unroll 2
    for (int c16 = 0; c16 < 16; c16++) {
        uint32_t pvA[4], pvB[4];
        #pragma unroll
        for (int sub = 0; sub < 2; sub++) {
            const uint32_t kf = KF[2*c16 + sub][lane];
            {   // block A: logits = (q_hi + q_lo) * k  in ONE k16 MMA
                float s0=0.f,s1=0.f,s2=0.f,s3=0.f;
                MMAF16(s0,s1,s2,s3, aA0,aA1,aA2,aA3, kf, kf);
                float p0=ex2f(s0), p1=ex2f(s1), p2=ex2f(s2), p3=ex2f(s3);
                rsA0 += p0 + p1;  rsA1 += p2 + p3;
                pvA[2*sub]   = f16p(p0, p1);
                pvA[2*sub+1] = f16p(p2, p3);
            }
            {   // block B
                float s0=0.f,s1=0.f,s2=0.f,s3=0.f;
                MMAF16(s0,s1,s2,s3, aB0,aB1,aB2,aB3, kf, kf);
                float p0=ex2f(s0), p1=ex2f(s1), p2=ex2f(s2), p3=ex2f(s3);
                rsB0 += p0 + p1;  rsB1 += p2 + p3;
                pvB[2*sub]   = f16p(p0, p1);
                pvB[2*sub+1] = f16p(p2, p3);
            }
        }
        const uint2 vf = VF[c16][lane];
        MMAF16(mA0,mA1,mA2,mA3, pvA[0],pvA[1],pvA[2],pvA[3], vf.x, vf.y);
        MMAF16(mB0,mB1,mB2,mB3, pvB[0],pvB[1],pvB[2],pvB[3], vf.x, vf.y);
    }

    // row sums: quad butterfly
    #pragma unroll
    for (int x = 1; x <= 2; x <<= 1) {
        rsA0 += __shfl_xor_sync(0xffffffffu, rsA0, x);
        rsA1 += __shfl_xor_sync(0xffffffffu, rsA1, x);
        rsB0 += __shfl_xor_sync(0xffffffffu, rsB0, x);
        rsB1 += __shfl_xor_sync(0xffffffffu, rsB1, x);
    }

    // ---- epilogue: lane owns 4 rows x (d = 2q, 2q+1) ----
    float2 wp[9];
    #pragma unroll
    for (int tap = 0; tap < 9; tap++) wp[tap] = *(const float2*)&wS[tap*8 + 2*q];
    const float2 bias = *(const float2*)&bS[2*q];

    const float oc[4][2] = {
        { mA0 / rsA0, mA1 / rsA0 },
        { mA2 / rsA1, mA3 / rsA1 },
        { mB0 / rsB0, mB1 / rsB0 },
        { mB2 / rsB1, mB3 / rsB1 },
    };
    const int rows[4] = { R0 + g, R0 + g + 8, R1 + g, R1 + g + 8 };

    #pragma unroll
    for (int ri = 0; ri < 4; ri++) {
        const int tok = rows[ri];
        const int y  = tok >> 1;
        const int xi = tok & 1;
        float rx = bias.x, ry = bias.y;
        #pragma unroll
        for (int ky = 0; ky < 3; ky++) {
            #pragma unroll
            for (int kx = 0; kx < 3; kx++) {
                int dxi = xi + kx - 1;
                if (dxi >= 0 && dxi <= 1) {
                    int ptok = tok + (ky - 1)*2 + (kx - 1) + 3;
                    float2 v = *(const float2*)&vS[ptok*8 + 2*q];
                    float2 wv = wp[ky*3 + kx];
                    rx += v.x * wv.x;
                    ry += v.y * wv.y;
                }
            }
        }
        const size_t obase = ((size_t)b*HW_ + (size_t)y*WW_ + 2*wx + xi)*CC_ + h*8 + 2*q;
        *(float2*)(out + obase) = make_float2(oc[ri][0] + rx, oc[ri][1] + ry);
    }
}

extern "C" void kernel_launch(void* const* d_in, const int* in_sizes, int n_in,
                              void* d_out, int out_size)
{
    const float* temp = (const float*)d_in[0];
    const float* cw   = (const float*)d_in[1];
    const float* cb   = (const float*)d_in[2];
    float* out        = (float*)d_out;
    lepe_mma5<<<2048, 256>>>(temp, cw, cb, out);
}

// round 14
// speedup vs baseline: 4.4094x; 1.0714x over previous
#include <cuda_runtime.h>
#include <cuda_fp16.h>
#include <cstdint>

// LePEAttention R14: window-PAIR CTAs. R13's binder was load-phase LDG
// wavefronts: one window is only 8B wide per image row (x-pair) in the
// channel-major input -> 16 lines per warp-LDG. A CTA owning two adjacent
// windows reads 16 contiguous B/row -> 8 lines per warp-LDG (halved).
// grid 1024 = (b, wp, h), 512 thr: warps 0-7 compute window 0, 8-15 window 1;
// per-warp compute identical to R13 (fp16 dual-packed QK, fp16 PV, m16n8k16).
// B=4, C=64, H=W=128, NUM_HEADS=8, hd=8, window 128x2 = 256 tokens.

#define HW_ 16384
#define WW_ 128
#define CC_ 64

__device__ __forceinline__ float ex2f(float x) { float r; asm("ex2.approx.f32 %0,%1;" : "=f"(r) : "f"(x)); return r; }
// pack fp16x2 {lower16 = fp16(lo_elem), upper16 = fp16(hi_elem)}
__device__ __forceinline__ uint32_t f16p(float lo_elem, float hi_elem) {
    uint32_t r; asm("cvt.rn.f16x2.f32 %0, %1, %2;" : "=r"(r) : "f"(hi_elem), "f"(lo_elem)); return r;
}
__device__ __forceinline__ float f16rt(float v) { return __half2float(__float2half_rn(v)); }

#define MMAF16(c0,c1,c2,c3, a0,a1,a2,a3, b0,b1) \
    asm volatile("mma.sync.aligned.m16n8k16.row.col.f32.f16.f16.f32 " \
        "{%0,%1,%2,%3}, {%4,%5,%6,%7}, {%8,%9}, {%0,%1,%2,%3};" \
        : "+f"(c0), "+f"(c1), "+f"(c2), "+f"(c3) \
        : "r"(a0), "r"(a1), "r"(a2), "r"(a3), "r"(b0), "r"(b1))

__global__ void __launch_bounds__(512, 2)
lepe_mma6(const float* __restrict__ temp,
          const float* __restrict__ cw,
          const float* __restrict__ cb,
          float* __restrict__ out)
{
    const int bid = blockIdx.x;        // 0..1023 = (b, wp, h)
    const int h   = bid & 7;
    const int grp = bid >> 3;          // 0..127
    const int b   = grp >> 5;
    const int wp  = grp & 31;          // window pair: windows 2wp, 2wp+1
    const int x0  = 4*wp;              // x range [x0, x0+4)

    const int tid  = threadIdx.x;      // 0..511
    const int lane = tid & 31;
    const int w    = tid >> 5;         // 0..15
    const int g    = lane >> 2;
    const int q    = lane & 3;

    // Per-window arrays, [2] indexed by window-in-pair.
    // KF[wi][t][lane] = fp16x2 of k[8t+g][d=2q,2q+1]
    // VF[wi][c][lane] = {b0,b1} fp16 V fragments, d = g
    // QS[wi][m*8+0..3] = q_hi fp16x2 pairs; +4..7 = q_lo pairs
    __shared__ __align__(16) uint32_t KF[2][32][32];   // 8 KB
    __shared__ __align__(16) uint2    VF[2][16][32];   // 8 KB
    __shared__ __align__(16) uint32_t QS[2][256*8];    // 16 KB
    __shared__ __align__(16) float    vS[2][262*8];    // 16.8 KB
    __shared__ float wS[72];
    __shared__ float bS[8];

    if (tid < 48) {
        const int wi = tid / 24, r = tid % 24;
        vS[wi][r] = 0.f; vS[wi][262*8 - 24 + r] = 0.f;
    }
    if (tid < 72) wS[tid] = cw[(h*8 + (tid & 7))*9 + (tid >> 3)];   // wS[tap*8+d]
    if (tid < 8)  bS[tid] = cb[h*8 + tid];

    const float qscale = 0.35355339059327373f * 1.44269504088896340736f; // 8^-0.5 * log2(e)

    // ---- joint coalesced load: thread -> (y = tid>>2, xl = tid&3) ----
    // xl covers 16 contiguous bytes per row spanning both windows.
    const int ly  = tid >> 2;          // image row 0..127
    const int xl  = tid & 3;
    const int wi0 = xl >> 1;           // which window this thread's value belongs to
    const int tok = ly*2 + (xl & 1);   // token within that window
    const size_t gbase = (size_t)ly*WW_ + (x0 + xl);

    // Q
    {
        const float* qg = temp + ((size_t)(b*3 + 0)*CC_ + h*8)*HW_ + gbase;
        float v[8], hi[8];
        #pragma unroll
        for (int d = 0; d < 8; d++) {
            v[d]  = qg[(size_t)d*HW_] * qscale;
            hi[d] = f16rt(v[d]);
        }
        #pragma unroll
        for (int j = 0; j < 4; j++) {
            QS[wi0][tok*8 + j]     = f16p(hi[2*j], hi[2*j + 1]);
            QS[wi0][tok*8 + 4 + j] = f16p(v[2*j] - hi[2*j], v[2*j + 1] - hi[2*j + 1]);
        }
    }
    // K
    {
        const float* kg = temp + ((size_t)(b*3 + 1)*CC_ + h*8)*HW_ + gbase;
        float kv[8];
        #pragma unroll
        for (int d = 0; d < 8; d++) kv[d] = kg[(size_t)d*HW_];
        const int t = tok >> 3, gg = tok & 7;
        #pragma unroll
        for (int qq = 0; qq < 4; qq++)
            KF[wi0][t][gg*4 + qq] = f16p(kv[2*qq], kv[2*qq + 1]);
    }
    // V exact
    {
        const float* vg = temp + ((size_t)(b*3 + 2)*CC_ + h*8)*HW_ + gbase;
        #pragma unroll
        for (int d = 0; d < 8; d++)
            vS[wi0][(tok + 3)*8 + d] = vg[(size_t)d*HW_];
    }
    __syncthreads();

    // ---- V fp16 fragment packing: threads 0-255, 128 per window ----
    if (tid < 256) {
        const int wi = tid >> 7;
        const int u  = tid & 127;
        const int c = u >> 3, p = u & 7;
        const float* v0 = &vS[wi][(2*u + 3)*8];
        const float* v1 = &vS[wi][(2*u + 4)*8];
        uint32_t* VFu = (uint32_t*)&VF[wi][0][0];
        #pragma unroll
        for (int d = 0; d < 8; d++) {
            uint32_t pk = f16p(v0[d], v1[d]);
            int lane_t = d*4 + (p & 3);
            int fld    = (p < 4) ? 0 : 1;
            VFu[(c*32 + lane_t)*2 + fld] = pk;
        }
    }
    __syncthreads();

    // ---- compute: warps 0-7 -> window 0, warps 8-15 -> window 1 ----
    const int wi = w >> 3;
    const int wl = w & 7;
    const uint32_t* QSw = QS[wi];
    const float*    vSw = vS[wi];

    const int R0 = wl*32, R1 = wl*32 + 16;
    const uint32_t aA0 = QSw[(R0 + g    )*8 + q];
    const uint32_t aA1 = QSw[(R0 + g + 8)*8 + q];
    const uint32_t aA2 = QSw[(R0 + g    )*8 + 4 + q];
    const uint32_t aA3 = QSw[(R0 + g + 8)*8 + 4 + q];
    const uint32_t aB0 = QSw[(R1 + g    )*8 + q];
    const uint32_t aB1 = QSw[(R1 + g + 8)*8 + q];
    const uint32_t aB2 = QSw[(R1 + g    )*8 + 4 + q];
    const uint32_t aB3 = QSw[(R1 + g + 8)*8 + 4 + q];

    float mA0=0.f,mA1=0.f,mA2=0.f,mA3=0.f;
    float mB0=0.f,mB1=0.f,mB2=0.f,mB3=0.f;
    float rsA0=0.f, rsA1=0.f, rsB0=0.f, rsB1=0.f;

    #pragma unroll 2
    for (int c16 = 0; c16 < 16; c16++) {
        uint32_t pvA[4], pvB[4];
        #pragma unroll
        for (int sub = 0; sub < 2; sub++) {
            const uint32_t kf = KF[wi][2*c16 + sub][lane];
            {
                float s0=0.f,s1=0.f,s2=0.f,s3=0.f;
                MMAF16(s0,s1,s2,s3, aA0,aA1,aA2,aA3, kf, kf);
                float p0=ex2f(s0), p1=ex2f(s1), p2=ex2f(s2), p3=ex2f(s3);
                rsA0 += p0 + p1;  rsA1 += p2 + p3;
                pvA[2*sub]   = f16p(p0, p1);
                pvA[2*sub+1] = f16p(p2, p3);
            }
            {
                float s0=0.f,s1=0.f,s2=0.f,s3=0.f;
                MMAF16(s0,s1,s2,s3, aB0,aB1,aB2,aB3, kf, kf);
                float p0=ex2f(s0), p1=ex2f(s1), p2=ex2f(s2), p3=ex2f(s3);
                rsB0 += p0 + p1;  rsB1 += p2 + p3;
                pvB[2*sub]   = f16p(p0, p1);
                pvB[2*sub+1] = f16p(p2, p3);
            }
        }
        const uint2 vf = VF[wi][c16][lane];
        MMAF16(mA0,mA1,mA2,mA3, pvA[0],pvA[1],pvA[2],pvA[3], vf.x, vf.y);
        MMAF16(mB0,mB1,mB2,mB3, pvB[0],pvB[1],pvB[2],pvB[3], vf.x, vf.y);
    }

    // row sums: quad butterfly
    #pragma unroll
    for (int x = 1; x <= 2; x <<= 1) {
        rsA0 += __shfl_xor_sync(0xffffffffu, rsA0, x);
        rsA1 += __shfl_xor_sync(0xffffffffu, rsA1, x);
        rsB0 += __shfl_xor_sync(0xffffffffu, rsB0, x);
        rsB1 += __shfl_xor_sync(0xffffffffu, rsB1, x);
    }

    // ---- epilogue: lane owns 4 rows x (d = 2q, 2q+1) ----
    float2 wp9[9];
    #pragma unroll
    for (int tap = 0; tap < 9; tap++) wp9[tap] = *(const float2*)&wS[tap*8 + 2*q];
    const float2 bias = *(const float2*)&bS[2*q];

    const float oc[4][2] = {
        { mA0 / rsA0, mA1 / rsA0 },
        { mA2 / rsA1, mA3 / rsA1 },
        { mB0 / rsB0, mB1 / rsB0 },
        { mB2 / rsB1, mB3 / rsB1 },
    };
    const int rows[4] = { R0 + g, R0 + g + 8, R1 + g, R1 + g + 8 };
    const int xw = x0 + wi*2;          // x base of this warp's window

    #pragma unroll
    for (int ri = 0; ri < 4; ri++) {
        const int tk = rows[ri];
        const int y  = tk >> 1;
        const int xi = tk & 1;
        float rx = bias.x, ry = bias.y;
        #pragma unroll
        for (int ky = 0; ky < 3; ky++) {
            #pragma unroll
            for (int kx = 0; kx < 3; kx++) {
                int dxi = xi + kx - 1;
                if (dxi >= 0 && dxi <= 1) {
                    int ptok = tk + (ky - 1)*2 + (kx - 1) + 3;
                    float2 v = *(const float2*)&vSw[ptok*8 + 2*q];
                    float2 wv = wp9[ky*3 + kx];
                    rx += v.x * wv.x;
                    ry += v.y * wv.y;
                }
            }
        }
        const size_t obase = ((size_t)b*HW_ + (size_t)y*WW_ + xw + xi)*CC_ + h*8 + 2*q;
        *(float2*)(out + obase) = make_float2(oc[ri][0] + rx, oc[ri][1] + ry);
    }
}

extern "C" void kernel_launch(void* const* d_in, const int* in_sizes, int n_in,
                              void* d_out, int out_size)
{
    const float* temp = (const float*)d_in[0];
    const float* cw   = (const float*)d_in[1];
    const float* cb   = (const float*)d_in[2];
    float* out        = (float*)d_out;
    lepe_mma6<<<1024, 512>>>(temp, cw, cb, out);
}

// round 15
// speedup vs baseline: 5.6120x; 1.2727x over previous
#include <cuda_runtime.h>
#include <cuda_fp16.h>
#include <cstdint>

// LePEAttention R15: R14 (window-pair CTAs) + vectorized softmax + tensorized
// row-sums. Inner loop was issue-bound (~49 instr/c16): now (1) logits packed
// fp16x2 -> ex2.approx.f16x2 produces the PV A-fragment directly (4 ex2 + 2
// pack -> 2 pack + 2 ex2x2 per sub-block); (2) row-sums via an extra MMA with
// B=ones (fp16 1.0): the MMA k-reduction yields FULL row sums in the C-frag ->
// kills 16 fadds/c16 AND the quad butterfly, and num/denom consume identical
// fp16 p registers (exactly consistent softmax). ~27 instr/c16.
// grid 1024 = (b, window-pair, h), 512 thr; warps 0-7 window 0, 8-15 window 1.

#define HW_ 16384
#define WW_ 128
#define CC_ 64

__device__ __forceinline__ uint32_t f16p(float lo_elem, float hi_elem) {
    uint32_t r; asm("cvt.rn.f16x2.f32 %0, %1, %2;" : "=r"(r) : "f"(hi_elem), "f"(lo_elem)); return r;
}
__device__ __forceinline__ uint32_t ex2h2(uint32_t s) {
    uint32_t r; asm("ex2.approx.f16x2 %0, %1;" : "=r"(r) : "r"(s)); return r;
}
__device__ __forceinline__ float f16rt(float v) { return __half2float(__float2half_rn(v)); }

#define MMAF16(c0,c1,c2,c3, a0,a1,a2,a3, b0,b1) \
    asm volatile("mma.sync.aligned.m16n8k16.row.col.f32.f16.f16.f32 " \
        "{%0,%1,%2,%3}, {%4,%5,%6,%7}, {%8,%9}, {%0,%1,%2,%3};" \
        : "+f"(c0), "+f"(c1), "+f"(c2), "+f"(c3) \
        : "r"(a0), "r"(a1), "r"(a2), "r"(a3), "r"(b0), "r"(b1))

__global__ void __launch_bounds__(512, 2)
lepe_mma7(const float* __restrict__ temp,
          const float* __restrict__ cw,
          const float* __restrict__ cb,
          float* __restrict__ out)
{
    const int bid = blockIdx.x;        // 0..1023 = (b, wp, h)
    const int h   = bid & 7;
    const int grp = bid >> 3;
    const int b   = grp >> 5;
    const int wp  = grp & 31;          // window pair: windows 2wp, 2wp+1
    const int x0  = 4*wp;

    const int tid  = threadIdx.x;      // 0..511
    const int lane = tid & 31;
    const int w    = tid >> 5;         // 0..15
    const int g    = lane >> 2;
    const int q    = lane & 3;

    __shared__ __align__(16) uint32_t KF[2][32][32];   // 8 KB
    __shared__ __align__(16) uint2    VF[2][16][32];   // 8 KB
    __shared__ __align__(16) uint32_t QS[2][256*8];    // 16 KB
    __shared__ __align__(16) float    vS[2][262*8];    // 16.8 KB
    __shared__ float wS[72];
    __shared__ float bS[8];

    if (tid < 48) {
        const int wi = tid / 24, r = tid % 24;
        vS[wi][r] = 0.f; vS[wi][262*8 - 24 + r] = 0.f;
    }
    if (tid < 72) wS[tid] = cw[(h*8 + (tid & 7))*9 + (tid >> 3)];   // wS[tap*8+d]
    if (tid < 8)  bS[tid] = cb[h*8 + tid];

    const float qscale = 0.35355339059327373f * 1.44269504088896340736f; // 8^-0.5 * log2(e)

    // ---- joint coalesced load: thread -> (y = tid>>2, xl = tid&3) ----
    const int ly  = tid >> 2;
    const int xl  = tid & 3;
    const int wi0 = xl >> 1;
    const int tok = ly*2 + (xl & 1);
    const size_t gbase = (size_t)ly*WW_ + (x0 + xl);

    // Q: fp16 hi/lo packed pairs
    {
        const float* qg = temp + ((size_t)(b*3 + 0)*CC_ + h*8)*HW_ + gbase;
        float v[8], hi[8];
        #pragma unroll
        for (int d = 0; d < 8; d++) {
            v[d]  = qg[(size_t)d*HW_] * qscale;
            hi[d] = f16rt(v[d]);
        }
        #pragma unroll
        for (int j = 0; j < 4; j++) {
            QS[wi0][tok*8 + j]     = f16p(hi[2*j], hi[2*j + 1]);
            QS[wi0][tok*8 + 4 + j] = f16p(v[2*j] - hi[2*j], v[2*j + 1] - hi[2*j + 1]);
        }
    }
    // K: fp16 fragment-order
    {
        const float* kg = temp + ((size_t)(b*3 + 1)*CC_ + h*8)*HW_ + gbase;
        float kv[8];
        #pragma unroll
        for (int d = 0; d < 8; d++) kv[d] = kg[(size_t)d*HW_];
        const int t = tok >> 3, gg = tok & 7;
        #pragma unroll
        for (int qq = 0; qq < 4; qq++)
            KF[wi0][t][gg*4 + qq] = f16p(kv[2*qq], kv[2*qq + 1]);
    }
    // V exact
    {
        const float* vg = temp + ((size_t)(b*3 + 2)*CC_ + h*8)*HW_ + gbase;
        #pragma unroll
        for (int d = 0; d < 8; d++)
            vS[wi0][(tok + 3)*8 + d] = vg[(size_t)d*HW_];
    }
    __syncthreads();

    // ---- V fp16 fragment packing: threads 0-255, 128 per window ----
    if (tid < 256) {
        const int wi = tid >> 7;
        const int u  = tid & 127;
        const int c = u >> 3, p = u & 7;
        const float* v0 = &vS[wi][(2*u + 3)*8];
        const float* v1 = &vS[wi][(2*u + 4)*8];
        uint32_t* VFu = (uint32_t*)&VF[wi][0][0];
        #pragma unroll
        for (int d = 0; d < 8; d++) {
            uint32_t pk = f16p(v0[d], v1[d]);
            int lane_t = d*4 + (p & 3);
            int fld    = (p < 4) ? 0 : 1;
            VFu[(c*32 + lane_t)*2 + fld] = pk;
        }
    }
    __syncthreads();

    // ---- compute: warps 0-7 -> window 0, warps 8-15 -> window 1 ----
    const int wi = w >> 3;
    const int wl = w & 7;
    const uint32_t* QSw = QS[wi];
    const float*    vSw = vS[wi];

    const int R0 = wl*32, R1 = wl*32 + 16;
    const uint32_t aA0 = QSw[(R0 + g    )*8 + q];
    const uint32_t aA1 = QSw[(R0 + g + 8)*8 + q];
    const uint32_t aA2 = QSw[(R0 + g    )*8 + 4 + q];
    const uint32_t aA3 = QSw[(R0 + g + 8)*8 + 4 + q];
    const uint32_t aB0 = QSw[(R1 + g    )*8 + q];
    const uint32_t aB1 = QSw[(R1 + g + 8)*8 + q];
    const uint32_t aB2 = QSw[(R1 + g    )*8 + 4 + q];
    const uint32_t aB3 = QSw[(R1 + g + 8)*8 + 4 + q];
    const uint32_t ONES = 0x3C003C00u;   // fp16x2 (1.0, 1.0)

    float mA0=0.f,mA1=0.f,mA2=0.f,mA3=0.f;   // PV numerator frags
    float mB0=0.f,mB1=0.f,mB2=0.f,mB3=0.f;
    float rA0=0.f,rA1=0.f,rA2=0.f,rA3=0.f;   // row-sum frags (B = ones)
    float rB0=0.f,rB1=0.f,rB2=0.f,rB3=0.f;

    #pragma unroll 2
    for (int c16 = 0; c16 < 16; c16++) {
        uint32_t pvA[4], pvB[4];
        #pragma unroll
        for (int sub = 0; sub < 2; sub++) {
            const uint32_t kf = KF[wi][2*c16 + sub][lane];
            {
                float s0=0.f,s1=0.f,s2=0.f,s3=0.f;
                MMAF16(s0,s1,s2,s3, aA0,aA1,aA2,aA3, kf, kf);
                pvA[2*sub]   = ex2h2(f16p(s0, s1));
                pvA[2*sub+1] = ex2h2(f16p(s2, s3));
            }
            {
                float s0=0.f,s1=0.f,s2=0.f,s3=0.f;
                MMAF16(s0,s1,s2,s3, aB0,aB1,aB2,aB3, kf, kf);
                pvB[2*sub]   = ex2h2(f16p(s0, s1));
                pvB[2*sub+1] = ex2h2(f16p(s2, s3));
            }
        }
        const uint2 vf = VF[wi][c16][lane];
        MMAF16(mA0,mA1,mA2,mA3, pvA[0],pvA[1],pvA[2],pvA[3], vf.x, vf.y);
        MMAF16(rA0,rA1,rA2,rA3, pvA[0],pvA[1],pvA[2],pvA[3], ONES, ONES);
        MMAF16(mB0,mB1,mB2,mB3, pvB[0],pvB[1],pvB[2],pvB[3], vf.x, vf.y);
        MMAF16(rB0,rB1,rB2,rB3, pvB[0],pvB[1],pvB[2],pvB[3], ONES, ONES);
    }
    // rA0 = full row-sum of row R0+g, rA2 = row R0+g+8 (all ones-cols equal);
    // same for B block. No butterfly needed: MMA reduced over all keys.

    // ---- epilogue: lane owns 4 rows x (d = 2q, 2q+1) ----
    float2 wp9[9];
    #pragma unroll
    for (int tap = 0; tap < 9; tap++) wp9[tap] = *(const float2*)&wS[tap*8 + 2*q];
    const float2 bias = *(const float2*)&bS[2*q];

    const float oc[4][2] = {
        { mA0 / rA0, mA1 / rA0 },
        { mA2 / rA2, mA3 / rA2 },
        { mB0 / rB0, mB1 / rB0 },
        { mB2 / rB2, mB3 / rB2 },
    };
    const int rows[4] = { R0 + g, R0 + g + 8, R1 + g, R1 + g + 8 };
    const int xw = x0 + wi*2;

    #pragma unroll
    for (int ri = 0; ri < 4; ri++) {
        const int tk = rows[ri];
        const int y  = tk >> 1;
        const int xi = tk & 1;
        float rx = bias.x, ry = bias.y;
        #pragma unroll
        for (int ky = 0; ky < 3; ky++) {
            #pragma unroll
            for (int kx = 0; kx < 3; kx++) {
                int dxi = xi + kx - 1;
                if (dxi >= 0 && dxi <= 1) {
                    int ptok = tk + (ky - 1)*2 + (kx - 1) + 3;
                    float2 v = *(const float2*)&vSw[ptok*8 + 2*q];
                    float2 wv = wp9[ky*3 + kx];
                    rx += v.x * wv.x;
                    ry += v.y * wv.y;
                }
            }
        }
        const size_t obase = ((size_t)b*HW_ + (size_t)y*WW_ + xw + xi)*CC_ + h*8 + 2*q;
        *(float2*)(out + obase) = make_float2(oc[ri][0] + rx, oc[ri][1] + ry);
    }
}

extern "C" void kernel_launch(void* const* d_in, const int* in_sizes, int n_in,
                              void* d_out, int out_size)
{
    const float* temp = (const float*)d_in[0];
    const float* cw   = (const float*)d_in[1];
    const float* cb   = (const float*)d_in[2];
    float* out        = (float*)d_out;
    lepe_mma7<<<1024, 512>>>(temp, cw, cb, out);
}